// round 15
// baseline (speedup 1.0000x reference)
#include <cuda_runtime.h>
#include <cuda_bf16.h>
#include <cstdint>
#include <math.h>

// Problem constants (B=2, C=128, H=64, W=64)
#define NPIX 8192
#define CDIM 128
#define HW   4096
#define CHW  524288
#define EXP_SCALE 20.609929155556625f   // (1/0.07) * log2(e), folded into A rows

// ---------------- scratch (device globals; no allocation allowed) -------------
__device__ __nv_bfloat16 gA[NPIX * CDIM];  // input rows (pre-scaled) -> rows of D
__device__ __nv_bfloat16 gB[NPIX * CDIM];  // target rows            -> cols of D
__device__ float gS[2 * NPIX];             // [0]=total sums, [1]=match sums

// dynamic smem layout
#define SM_A     0        // 32KB: A chunks kc0 [0,16K), kc1 [16K,32K)
#define SM_B     32768    // 4 ring slots x 16KB
#define SM_CLS_T 98304    // 1024 ints (4KB)
#define SM_CLS_I 102400   // 128 ints
#define SM_RED   102912   // float2[4][128] = 4KB
#define SM_TOTAL 107008

// ---------------- helpers -----------------------------------------------------
__device__ __forceinline__ uint32_t smem_u32(const void* p) {
    uint32_t a;
    asm("{ .reg .u64 t; cvta.to.shared.u64 t, %1; cvt.u32.u64 %0, t; }"
        : "=r"(a) : "l"(p));
    return a;
}

__device__ __forceinline__ void ldsm_x4(uint32_t& r0, uint32_t& r1, uint32_t& r2,
                                        uint32_t& r3, uint32_t a) {
    asm volatile("ldmatrix.sync.aligned.m8n8.x4.shared.b16 {%0,%1,%2,%3}, [%4];"
                 : "=r"(r0), "=r"(r1), "=r"(r2), "=r"(r3) : "r"(a));
}

__device__ __forceinline__ void mma16816(float* d, const uint32_t* a, const uint32_t* b) {
    asm volatile(
        "mma.sync.aligned.m16n8k16.row.col.f32.bf16.bf16.f32 "
        "{%0,%1,%2,%3}, {%4,%5,%6,%7}, {%8,%9}, {%0,%1,%2,%3};"
        : "+f"(d[0]), "+f"(d[1]), "+f"(d[2]), "+f"(d[3])
        : "r"(a[0]), "r"(a[1]), "r"(a[2]), "r"(a[3]), "r"(b[0]), "r"(b[1]));
}

__device__ __forceinline__ float ex2f(float x) {
    float r;
    asm("ex2.approx.f32 %0, %1;" : "=f"(r) : "f"(x));
    return r;
}

#define CP_COMMIT() asm volatile("cp.async.commit_group;" ::: "memory")
#define CP_WAIT(n)  asm volatile("cp.async.wait_group %0;" :: "n"(n) : "memory")

// stage full A tile (128 rows x K128) into [0,32K): 8 cp.async per thread
__device__ __forceinline__ void stage_A(uint32_t sbase, int tid, int bx) {
    const __nv_bfloat16* Abase = gA + (size_t)bx * 128 * CDIM;
    #pragma unroll
    for (int t = 0; t < 8; t++) {
        int i    = tid + t * 256;        // 0..2047
        int kc   = i >> 10;              // A chunk 0/1
        int rrem = i & 1023;
        int row  = rrem >> 3;            // 0..127
        int c    = rrem & 7;             // 16B seg
        const __nv_bfloat16* g = Abase + (size_t)row * CDIM + kc * 64 + c * 8;
        uint32_t sa = sbase + kc * 16384 + row * 128 + ((c ^ (row & 7)) << 4);
        asm volatile("cp.async.cg.shared.global [%0], [%1], 16;" :: "r"(sa), "l"(g));
    }
}

// stage one B chunk (sub-tile n of 8, k-half kc) into ring slot: 4 cp.async/thread
__device__ __forceinline__ void stage_B(uint32_t sbase, int slot, int n, int kc,
                                        int tid, int by) {
    const __nv_bfloat16* Bbase = gB + (size_t)(by * 1024 + n * 128) * CDIM + kc * 64;
    uint32_t sb = sbase + SM_B + slot * 16384;
    #pragma unroll
    for (int t = 0; t < 4; t++) {
        int i   = tid + t * 256;        // 0..1023
        int row = i >> 3;               // 0..127
        int c   = i & 7;
        const __nv_bfloat16* g = Bbase + (size_t)row * CDIM + c * 8;
        uint32_t sa = sb + row * 128 + ((c ^ (row & 7)) << 4);
        asm volatile("cp.async.cg.shared.global [%0], [%1], 16;" :: "r"(sa), "l"(g));
    }
}

// ---------------- fused normalize (both tensors) + gS zero ---------------------
// 8 pixels per block, grid 2048. input rows pre-scaled by EXP_SCALE.
__global__ void norm_kernel(const float* __restrict__ in, const float* __restrict__ tg) {
    __shared__ float tile[CDIM][9];
    __shared__ float part[32][9];
    __shared__ float inv[8];

    const int blk   = blockIdx.x;
    const int which = blk >> 10;            // 0: input, 1: target
    const int sub   = blk & 1023;
    const float* src = which ? tg : in;
    __nv_bfloat16* dst = which ? gB : gA;
    const float postscale = which ? 1.0f : EXP_SCALE;

    const int tx = threadIdx.x;             // 0..7  pixel
    const int ty = threadIdx.y;             // 0..31 channel group
    const int tid = ty * 8 + tx;

    if (which == 0 && tid < 16)             // zero gS: 1024 blocks x 16 = 16384
        gS[sub * 16 + tid] = 0.0f;

    const int p0 = sub * 8;
    const int b  = p0 >> 12;
    const int hw = p0 & 4095;

    const float* base = src + (size_t)b * CHW + hw + tx;
    float ps = 0.0f;
    #pragma unroll
    for (int c = ty; c < CDIM; c += 32) {
        float v = base[c * HW];
        tile[c][tx] = v;
        ps += v * v;
    }
    part[ty][tx] = ps;
    __syncthreads();
    if (tid < 8) {
        float s = 0.0f;
        #pragma unroll
        for (int i = 0; i < 32; i++) s += part[i][tid];
        inv[tid] = rsqrtf(fmaxf(s, 1e-24f));
    }
    __syncthreads();

    #pragma unroll
    for (int idx = tid; idx < 8 * CDIM; idx += 256) {
        int pix = idx >> 7;
        int c   = idx & 127;
        dst[(size_t)(p0 + pix) * CDIM + c] =
            __float2bfloat16(tile[c][pix] * inv[pix] * postscale);
    }
}

// ---------------- 128x1024 macro-tile HMMA GEMM --------------------------------
// D[b, a] = scaled_input_row(b) . target_row(a); rows=input (pi), cols=target (pt)
// 8 sequential 128x128 sub-tiles per CTA, A staged once.
__global__ __launch_bounds__(256, 2)
void gemm_kernel(const int* __restrict__ tseg, const int* __restrict__ iseg) {
    extern __shared__ char smem[];
    int*    cls_t = (int*)(smem + SM_CLS_T);     // 1024 target classes
    int*    cls_i = (int*)(smem + SM_CLS_I);     // 128 input classes
    float2* sRed  = (float2*)(smem + SM_RED);    // [4 warps-n][128 rows]

    const int tid  = threadIdx.x;
    const int wid  = tid >> 5;
    const int lane = tid & 31;
    const int bx = blockIdx.x, by = blockIdx.y;
    const uint32_t sbase = smem_u32(smem);

    #pragma unroll
    for (int i = tid; i < 1024; i += 256) cls_t[i] = tseg[by * 1024 + i];
    if (tid < 128) cls_i[tid] = iseg[bx * 128 + tid];

    // prolog: G0 = {A full, B0}, G1 = {B1}, G2 = {B2}
    stage_A(sbase, tid, bx);
    stage_B(sbase, 0, 0, 0, tid, by); CP_COMMIT();
    stage_B(sbase, 1, 0, 1, tid, by); CP_COMMIT();
    stage_B(sbase, 2, 1, 0, tid, by); CP_COMMIT();

    const int wm = wid >> 2;            // 0..1 (64 rows each)
    const int wn = wid & 3;             // 0..3 (32 cols each)
    const int ar = wm * 64 + (lane & 15);
    const int ah = lane >> 4;
    const int bc = wn * 32 + (lane & 7) + ((lane >> 4) << 3);
    const int bh = (lane >> 3) & 1;

    uint32_t aoff[4]; int arx[4];
    #pragma unroll
    for (int mt = 0; mt < 4; mt++) {
        int r = ar + mt * 16;
        aoff[mt] = r * 128;
        arx[mt]  = r & 7;
    }
    uint32_t boff[2]; int bcx[2];
    #pragma unroll
    for (int p = 0; p < 2; p++) {
        int c0 = bc + p * 16;
        boff[p] = c0 * 128;
        bcx[p]  = c0 & 7;
    }

    float acc[4][4][4];
    #pragma unroll
    for (int mt = 0; mt < 4; mt++)
        #pragma unroll
        for (int nt = 0; nt < 4; nt++)
            #pragma unroll
            for (int q = 0; q < 4; q++) acc[mt][nt][q] = 0.0f;

    float tS[8], mS[8];                 // per (mt,h) running sums over all 1024 cols
    #pragma unroll
    for (int i = 0; i < 8; i++) { tS[i] = 0.0f; mS[i] = 0.0f; }

    #pragma unroll
    for (int j = 0; j < 16; j++) {      // chunk step: sub-tile j>>1, k-half j&1
        if (j < 14)      CP_WAIT(2);
        else if (j == 14) CP_WAIT(1);
        else              CP_WAIT(0);
        __syncthreads();

        if (j < 13) {                   // prefetch B[j+3] into slot (j+3)&3
            const int jn = j + 3;
            stage_B(sbase, jn & 3, jn >> 1, jn & 1, tid, by);
            CP_COMMIT();
        }

        const uint32_t bbA = sbase + (j & 1) * 16384;
        const uint32_t bbB = sbase + SM_B + (j & 3) * 16384;

        // B-fragment double buffer: prefetch kkl=0 B frags
        uint32_t b[2][4][2];
        {
            const int cb = bh;
            #pragma unroll
            for (int p = 0; p < 2; p++)
                ldsm_x4(b[0][2 * p][0], b[0][2 * p][1], b[0][2 * p + 1][0],
                        b[0][2 * p + 1][1], bbB + boff[p] + ((cb ^ bcx[p]) << 4));
        }

        #pragma unroll
        for (int kkl = 0; kkl < 4; kkl++) {
            const int cur = kkl & 1;
            uint32_t a[4][4];
            const int ca = kkl * 2 + ah;
            #pragma unroll
            for (int mt = 0; mt < 4; mt++)
                ldsm_x4(a[mt][0], a[mt][1], a[mt][2], a[mt][3],
                        bbA + aoff[mt] + ((ca ^ arx[mt]) << 4));
            if (kkl < 3) {              // prefetch next k-step's B frags
                const int cb = (kkl + 1) * 2 + bh;
                #pragma unroll
                for (int p = 0; p < 2; p++)
                    ldsm_x4(b[cur ^ 1][2 * p][0], b[cur ^ 1][2 * p][1],
                            b[cur ^ 1][2 * p + 1][0], b[cur ^ 1][2 * p + 1][1],
                            bbB + boff[p] + ((cb ^ bcx[p]) << 4));
            }
            #pragma unroll
            for (int mt = 0; mt < 4; mt++)
                #pragma unroll
                for (int nt = 0; nt < 4; nt++)
                    mma16816(acc[mt][nt], a[mt], b[cur][nt]);
        }

        if (j & 1) {                    // sub-tile complete: fold into tS/mS
            const int n = j >> 1;
            const int* ct = cls_t + n * 128 + wn * 32 + (lane & 3) * 2;
            int cr[8];
            #pragma unroll
            for (int nt = 0; nt < 4; nt++) {
                cr[nt * 2]     = ct[nt * 8];
                cr[nt * 2 + 1] = ct[nt * 8 + 1];
            }
            #pragma unroll
            for (int mt = 0; mt < 4; mt++) {
                #pragma unroll
                for (int h = 0; h < 2; h++) {
                    const int r   = wm * 64 + mt * 16 + (lane >> 2) + h * 8;
                    const int myk = cls_i[r];
                    float tot = 0.f, mat = 0.f;
                    #pragma unroll
                    for (int nt = 0; nt < 4; nt++) {
                        #pragma unroll
                        for (int jj = 0; jj < 2; jj++) {
                            float e = ex2f(acc[mt][nt][h * 2 + jj]);  // scale pre-folded
                            tot += e;
                            mat += (cr[nt * 2 + jj] == myk) ? e : 0.f;
                        }
                    }
                    tS[mt * 2 + h] += tot;
                    mS[mt * 2 + h] += mat;
                }
            }
            #pragma unroll
            for (int mt = 0; mt < 4; mt++)
                #pragma unroll
                for (int nt = 0; nt < 4; nt++)
                    #pragma unroll
                    for (int q = 0; q < 4; q++) acc[mt][nt][q] = 0.0f;
        }
    }

    // ---- final reduce: quad shuffles once, cross-warp via smem, 2 atomics ----
    #pragma unroll
    for (int mt = 0; mt < 4; mt++) {
        #pragma unroll
        for (int h = 0; h < 2; h++) {
            float t = tS[mt * 2 + h], m = mS[mt * 2 + h];
            t += __shfl_xor_sync(0xffffffffu, t, 1);
            t += __shfl_xor_sync(0xffffffffu, t, 2);
            m += __shfl_xor_sync(0xffffffffu, m, 1);
            m += __shfl_xor_sync(0xffffffffu, m, 2);
            if ((lane & 3) == 0) {
                const int r = wm * 64 + mt * 16 + (lane >> 2) + h * 8;
                sRed[wn * 128 + r] = make_float2(t, m);
            }
        }
    }
    __syncthreads();

    if (tid < 128) {
        float t = 0.f, m = 0.f;
        #pragma unroll
        for (int w = 0; w < 4; w++) {
            float2 v = sRed[w * 128 + tid];
            t += v.x;
            m += v.y;
        }
        int bg = bx * 128 + tid;
        atomicAdd(&gS[bg], t);
        atomicAdd(&gS[NPIX + bg], m);
    }
}

// ---------------- final loss (single block, vectorized) ------------------------
__global__ void loss_kernel(float* __restrict__ out) {
    __shared__ float red[1024];
    const float4* den4 = (const float4*)gS;
    const float4* nom4 = (const float4*)(gS + NPIX);
    float s = 0.0f;
    #pragma unroll
    for (int it = 0; it < 2; it++) {
        int i = threadIdx.x + it * 1024;       // 2048 float4 pairs
        float4 d = den4[i];
        float4 n = nom4[i];
        s += -__logf(n.x / (d.x + 1e-8f)) - __logf(n.y / (d.y + 1e-8f))
           - __logf(n.z / (d.z + 1e-8f)) - __logf(n.w / (d.w + 1e-8f));
    }
    red[threadIdx.x] = s;
    __syncthreads();
    for (int st = 512; st > 0; st >>= 1) {
        if (threadIdx.x < st) red[threadIdx.x] += red[threadIdx.x + st];
        __syncthreads();
    }
    if (threadIdx.x == 0) out[0] = red[0] * (1.0f / (float)NPIX);
}

// ---------------- launch -------------------------------------------------------
extern "C" void kernel_launch(void* const* d_in, const int* in_sizes, int n_in,
                              void* d_out, int out_size) {
    const float* input  = (const float*)d_in[0];
    const float* target = (const float*)d_in[1];
    const int*   iseg   = (const int*)d_in[2];
    const int*   tseg   = (const int*)d_in[3];
    float* out = (float*)d_out;

    cudaFuncSetAttribute(gemm_kernel, cudaFuncAttributeMaxDynamicSharedMemorySize, SM_TOTAL);

    dim3 nb(8, 32);
    norm_kernel<<<2048, nb>>>(input, target);   // both tensors + gS zero

    dim3 grid(NPIX / 128, NPIX / 1024);
    gemm_kernel<<<grid, 256, SM_TOTAL>>>(tseg, iseg);

    loss_kernel<<<1, 1024>>>(out);
}

// round 16
// speedup vs baseline: 1.1144x; 1.1144x over previous
#include <cuda_runtime.h>
#include <cuda_bf16.h>
#include <cstdint>
#include <math.h>

// Problem constants (B=2, C=128, H=64, W=64)
#define NPIX 8192
#define CDIM 128
#define HW   4096
#define CHW  524288
#define EXP_SCALE 20.609929155556625f   // (1/0.07) * log2(e), folded into A rows

// ---------------- scratch (device globals; no allocation allowed) -------------
__device__ __nv_bfloat16 gA[NPIX * CDIM];  // input rows (pre-scaled) -> rows of D
__device__ __nv_bfloat16 gB[NPIX * CDIM];  // target rows            -> cols of D
__device__ float gS[2 * NPIX];             // [0]=total sums, [1]=match sums

// dynamic smem layout
#define SM_A     0        // 32KB: A chunks kc0 [0,16K), kc1 [16K,32K)
#define SM_B     32768    // 4 ring slots x 16KB
#define SM_CLS_T 98304    // 512 ints
#define SM_CLS_I 100352   // 128 ints
#define SM_RED   100864   // float2[4][128] = 4KB
#define SM_TOTAL 104960

// ---------------- helpers -----------------------------------------------------
__device__ __forceinline__ uint32_t smem_u32(const void* p) {
    uint32_t a;
    asm("{ .reg .u64 t; cvta.to.shared.u64 t, %1; cvt.u32.u64 %0, t; }"
        : "=r"(a) : "l"(p));
    return a;
}

__device__ __forceinline__ void ldsm_x4(uint32_t& r0, uint32_t& r1, uint32_t& r2,
                                        uint32_t& r3, uint32_t a) {
    asm volatile("ldmatrix.sync.aligned.m8n8.x4.shared.b16 {%0,%1,%2,%3}, [%4];"
                 : "=r"(r0), "=r"(r1), "=r"(r2), "=r"(r3) : "r"(a));
}

__device__ __forceinline__ void mma16816(float* d, const uint32_t* a, const uint32_t* b) {
    asm volatile(
        "mma.sync.aligned.m16n8k16.row.col.f32.bf16.bf16.f32 "
        "{%0,%1,%2,%3}, {%4,%5,%6,%7}, {%8,%9}, {%0,%1,%2,%3};"
        : "+f"(d[0]), "+f"(d[1]), "+f"(d[2]), "+f"(d[3])
        : "r"(a[0]), "r"(a[1]), "r"(a[2]), "r"(a[3]), "r"(b[0]), "r"(b[1]));
}

__device__ __forceinline__ float ex2f(float x) {
    float r;
    asm("ex2.approx.f32 %0, %1;" : "=f"(r) : "f"(x));
    return r;
}

#define CP_COMMIT() asm volatile("cp.async.commit_group;" ::: "memory")
#define CP_WAIT(n)  asm volatile("cp.async.wait_group %0;" :: "n"(n) : "memory")

// stage full A tile (128 rows x K128) into [0,32K): 8 cp.async per thread
__device__ __forceinline__ void stage_A(uint32_t sbase, int tid, int bx) {
    const __nv_bfloat16* Abase = gA + (size_t)bx * 128 * CDIM;
    #pragma unroll
    for (int t = 0; t < 8; t++) {
        int i    = tid + t * 256;        // 0..2047
        int kc   = i >> 10;              // A chunk 0/1
        int rrem = i & 1023;
        int row  = rrem >> 3;            // 0..127
        int c    = rrem & 7;             // 16B seg
        const __nv_bfloat16* g = Abase + (size_t)row * CDIM + kc * 64 + c * 8;
        uint32_t sa = sbase + kc * 16384 + row * 128 + ((c ^ (row & 7)) << 4);
        asm volatile("cp.async.cg.shared.global [%0], [%1], 16;" :: "r"(sa), "l"(g));
    }
}

// stage one B chunk (sub-tile n, k-half kc) into ring slot: 4 cp.async per thread
__device__ __forceinline__ void stage_B(uint32_t sbase, int slot, int n, int kc,
                                        int tid, int by) {
    const __nv_bfloat16* Bbase = gB + (size_t)(by * 512 + n * 128) * CDIM + kc * 64;
    uint32_t sb = sbase + SM_B + slot * 16384;
    #pragma unroll
    for (int t = 0; t < 4; t++) {
        int i   = tid + t * 256;        // 0..1023
        int row = i >> 3;               // 0..127
        int c   = i & 7;
        const __nv_bfloat16* g = Bbase + (size_t)row * CDIM + c * 8;
        uint32_t sa = sb + row * 128 + ((c ^ (row & 7)) << 4);
        asm volatile("cp.async.cg.shared.global [%0], [%1], 16;" :: "r"(sa), "l"(g));
    }
}

// ---------------- fused normalize (both tensors) + gS/out zero -----------------
// input rows additionally pre-scaled by EXP_SCALE so the gemm epilogue is
// exp2(acc) with no multiply.
__global__ void norm_kernel(const float* __restrict__ in, const float* __restrict__ tg,
                            float* __restrict__ out) {
    __shared__ float tile[CDIM][17];
    __shared__ float part[16][17];
    __shared__ float inv[16];

    const int blk   = blockIdx.x;
    const int which = blk >> 9;             // 0: input, 1: target
    const int sub   = blk & 511;
    const float* src = which ? tg : in;
    __nv_bfloat16* dst = which ? gB : gA;
    const float postscale = which ? 1.0f : EXP_SCALE;

    const int tx = threadIdx.x;             // 0..15 pixel
    const int ty = threadIdx.y;             // 0..15 channel group
    const int tid = ty * 16 + tx;

    if (which == 0 && tid < 32)             // zero gS: 512 blocks x 32 = 16384
        gS[sub * 32 + tid] = 0.0f;
    if (blk == 0 && tid == 0) out[0] = 0.0f;

    const int p0 = sub * 16;
    const int b  = p0 >> 12;
    const int hw = p0 & 4095;

    const float* base = src + (size_t)b * CHW + hw + tx;
    float ps = 0.0f;
    #pragma unroll
    for (int c = ty; c < CDIM; c += 16) {
        float v = base[c * HW];
        tile[c][tx] = v;
        ps += v * v;
    }
    part[ty][tx] = ps;
    __syncthreads();
    if (ty == 0) {
        float s = 0.0f;
        #pragma unroll
        for (int i = 0; i < 16; i++) s += part[i][tx];
        inv[tx] = rsqrtf(fmaxf(s, 1e-24f));
    }
    __syncthreads();

    #pragma unroll
    for (int idx = tid; idx < 16 * CDIM; idx += 256) {
        int pix = idx >> 7;
        int c   = idx & 127;
        dst[(size_t)(p0 + pix) * CDIM + c] =
            __float2bfloat16(tile[c][pix] * inv[pix] * postscale);
    }
}

// ---------------- 128x512 macro-tile HMMA GEMM ---------------------------------
// D[b, a] = scaled_input_row(b) . target_row(a); rows=input (pi), cols=target (pt)
__global__ __launch_bounds__(256, 2)
void gemm_kernel(const int* __restrict__ tseg, const int* __restrict__ iseg) {
    extern __shared__ char smem[];
    int*    cls_t = (int*)(smem + SM_CLS_T);     // 512 target classes
    int*    cls_i = (int*)(smem + SM_CLS_I);     // 128 input classes
    float2* sRed  = (float2*)(smem + SM_RED);    // [4 warps-n][128 rows]

    const int tid  = threadIdx.x;
    const int wid  = tid >> 5;
    const int lane = tid & 31;
    const int bx = blockIdx.x, by = blockIdx.y;
    const uint32_t sbase = smem_u32(smem);

    #pragma unroll
    for (int i = tid; i < 512; i += 256) cls_t[i] = tseg[by * 512 + i];
    if (tid < 128) cls_i[tid] = iseg[bx * 128 + tid];

    // prolog: G0 = {A full, B0}, G1 = {B1}, G2 = {B2}
    stage_A(sbase, tid, bx);
    stage_B(sbase, 0, 0, 0, tid, by); CP_COMMIT();
    stage_B(sbase, 1, 0, 1, tid, by); CP_COMMIT();
    stage_B(sbase, 2, 1, 0, tid, by); CP_COMMIT();

    const int wm = wid >> 2;            // 0..1 (64 rows each)
    const int wn = wid & 3;             // 0..3 (32 cols each)
    const int ar = wm * 64 + (lane & 15);
    const int ah = lane >> 4;
    const int bc = wn * 32 + (lane & 7) + ((lane >> 4) << 3);
    const int bh = (lane >> 3) & 1;

    uint32_t aoff[4]; int arx[4];
    #pragma unroll
    for (int mt = 0; mt < 4; mt++) {
        int r = ar + mt * 16;
        aoff[mt] = r * 128;
        arx[mt]  = r & 7;
    }
    uint32_t boff[2]; int bcx[2];
    #pragma unroll
    for (int p = 0; p < 2; p++) {
        int c0 = bc + p * 16;
        boff[p] = c0 * 128;
        bcx[p]  = c0 & 7;
    }

    float acc[4][4][4];
    #pragma unroll
    for (int mt = 0; mt < 4; mt++)
        #pragma unroll
        for (int nt = 0; nt < 4; nt++)
            #pragma unroll
            for (int q = 0; q < 4; q++) acc[mt][nt][q] = 0.0f;

    float tS[8], mS[8];                 // per (mt,h) running sums over all 512 cols
    #pragma unroll
    for (int i = 0; i < 8; i++) { tS[i] = 0.0f; mS[i] = 0.0f; }

    #pragma unroll
    for (int j = 0; j < 8; j++) {       // chunk step: sub-tile j>>1, k-half j&1
        if (j < 6)      CP_WAIT(2);
        else if (j == 6) CP_WAIT(1);
        else             CP_WAIT(0);
        __syncthreads();

        if (j < 5) {                    // prefetch B[j+3] into slot (j+3)&3
            const int jn = j + 3;
            stage_B(sbase, jn & 3, jn >> 1, jn & 1, tid, by);
            CP_COMMIT();
        }

        const uint32_t bbA = sbase + (j & 1) * 16384;
        const uint32_t bbB = sbase + SM_B + (j & 3) * 16384;

        // B-fragment double buffer: prefetch kkl=0 B frags
        uint32_t b[2][4][2];
        {
            const int cb = bh;
            #pragma unroll
            for (int p = 0; p < 2; p++)
                ldsm_x4(b[0][2 * p][0], b[0][2 * p][1], b[0][2 * p + 1][0],
                        b[0][2 * p + 1][1], bbB + boff[p] + ((cb ^ bcx[p]) << 4));
        }

        #pragma unroll
        for (int kkl = 0; kkl < 4; kkl++) {
            const int cur = kkl & 1;
            uint32_t a[4][4];
            const int ca = kkl * 2 + ah;
            #pragma unroll
            for (int mt = 0; mt < 4; mt++)
                ldsm_x4(a[mt][0], a[mt][1], a[mt][2], a[mt][3],
                        bbA + aoff[mt] + ((ca ^ arx[mt]) << 4));
            if (kkl < 3) {              // prefetch next k-step's B frags
                const int cb = (kkl + 1) * 2 + bh;
                #pragma unroll
                for (int p = 0; p < 2; p++)
                    ldsm_x4(b[cur ^ 1][2 * p][0], b[cur ^ 1][2 * p][1],
                            b[cur ^ 1][2 * p + 1][0], b[cur ^ 1][2 * p + 1][1],
                            bbB + boff[p] + ((cb ^ bcx[p]) << 4));
            }
            #pragma unroll
            for (int mt = 0; mt < 4; mt++)
                #pragma unroll
                for (int nt = 0; nt < 4; nt++)
                    mma16816(acc[mt][nt], a[mt], b[cur][nt]);
        }

        if (j & 1) {                    // sub-tile complete: fold into tS/mS
            const int n = j >> 1;
            const int* ct = cls_t + n * 128 + wn * 32 + (lane & 3) * 2;
            int cr[8];
            #pragma unroll
            for (int nt = 0; nt < 4; nt++) {
                cr[nt * 2]     = ct[nt * 8];
                cr[nt * 2 + 1] = ct[nt * 8 + 1];
            }
            #pragma unroll
            for (int mt = 0; mt < 4; mt++) {
                #pragma unroll
                for (int h = 0; h < 2; h++) {
                    const int r   = wm * 64 + mt * 16 + (lane >> 2) + h * 8;
                    const int myk = cls_i[r];
                    float tot = 0.f, mat = 0.f;
                    #pragma unroll
                    for (int nt = 0; nt < 4; nt++) {
                        #pragma unroll
                        for (int jj = 0; jj < 2; jj++) {
                            float e = ex2f(acc[mt][nt][h * 2 + jj]);  // scale pre-folded
                            tot += e;
                            mat += (cr[nt * 2 + jj] == myk) ? e : 0.f;
                        }
                    }
                    tS[mt * 2 + h] += tot;
                    mS[mt * 2 + h] += mat;
                }
            }
            #pragma unroll
            for (int mt = 0; mt < 4; mt++)
                #pragma unroll
                for (int nt = 0; nt < 4; nt++)
                    #pragma unroll
                    for (int q = 0; q < 4; q++) acc[mt][nt][q] = 0.0f;
        }
    }

    // ---- final reduce: quad shuffles once, cross-warp via smem, 2 atomics ----
    #pragma unroll
    for (int mt = 0; mt < 4; mt++) {
        #pragma unroll
        for (int h = 0; h < 2; h++) {
            float t = tS[mt * 2 + h], m = mS[mt * 2 + h];
            t += __shfl_xor_sync(0xffffffffu, t, 1);
            t += __shfl_xor_sync(0xffffffffu, t, 2);
            m += __shfl_xor_sync(0xffffffffu, m, 1);
            m += __shfl_xor_sync(0xffffffffu, m, 2);
            if ((lane & 3) == 0) {
                const int r = wm * 64 + mt * 16 + (lane >> 2) + h * 8;
                sRed[wn * 128 + r] = make_float2(t, m);
            }
        }
    }
    __syncthreads();

    if (tid < 128) {
        float t = 0.f, m = 0.f;
        #pragma unroll
        for (int w = 0; w < 4; w++) {
            float2 v = sRed[w * 128 + tid];
            t += v.x;
            m += v.y;
        }
        int bg = bx * 128 + tid;
        atomicAdd(&gS[bg], t);
        atomicAdd(&gS[NPIX + bg], m);
    }
}

// ---------------- final loss (16 blocks, atomic accumulate) --------------------
__global__ void loss_kernel(float* __restrict__ out) {
    __shared__ float red[512];
    const int b = blockIdx.x * 512 + threadIdx.x;
    float den = gS[b];
    float nom = gS[NPIX + b];
    red[threadIdx.x] = -__logf(nom / (den + 1e-8f));
    __syncthreads();
    for (int st = 256; st > 0; st >>= 1) {
        if (threadIdx.x < st) red[threadIdx.x] += red[threadIdx.x + st];
        __syncthreads();
    }
    if (threadIdx.x == 0) atomicAdd(out, red[0] * (1.0f / (float)NPIX));
}

// ---------------- launch -------------------------------------------------------
extern "C" void kernel_launch(void* const* d_in, const int* in_sizes, int n_in,
                              void* d_out, int out_size) {
    const float* input  = (const float*)d_in[0];
    const float* target = (const float*)d_in[1];
    const int*   iseg   = (const int*)d_in[2];
    const int*   tseg   = (const int*)d_in[3];
    float* out = (float*)d_out;

    cudaFuncSetAttribute(gemm_kernel, cudaFuncAttributeMaxDynamicSharedMemorySize, SM_TOTAL);

    dim3 nb(16, 16);
    norm_kernel<<<1024, nb>>>(input, target, out);   // both tensors + gS/out zero

    dim3 grid(NPIX / 128, NPIX / 512);
    gemm_kernel<<<grid, 256, SM_TOTAL>>>(tseg, iseg);

    loss_kernel<<<16, 512>>>(out);
}